// round 8
// baseline (speedup 1.0000x reference)
#include <cuda_runtime.h>
#include <cub/cub.cuh>
#include <cstdint>

namespace {
constexpr int BATCH = 8;
constexpr int NANCH = 262144;         // 2^18
constexpr int TOTAL = BATCH * NANCH;  // 2,097,152
constexpr int TOPK  = 6000;
constexpr int NOUT  = 1000;
constexpr int COLB  = (TOPK + 63) / 64;            // 94
constexpr float THR = 0.7f;
constexpr int TAIL_BITS = TOPK - (COLB - 1) * 64;  // 48
constexpr int HBINS = 32768;   // bucket = float_bits >> 15 (scores in (0,1))
constexpr int CAP   = 16384;   // per-batch candidate capacity (expected ~6400)
constexpr int FTHREADS = 1024; // fused NMS block size
// fused smem: boxes[TOPK] float4 + alive[COLB] u64 + diag[64] u64
//             + diagbytes[512] + kept[NOUT] int + ctrl[4]
constexpr int FUSED_SMEM = TOPK * 16 + COLB * 8 + 64 * 8 + 512 + NOUT * 4 + 16;
}

// -------- device-global scratch (no allocation allowed) ----------------------
__device__ int                g_hist[BATCH * HBINS];
__device__ int                g_thresh[BATCH];
__device__ int                g_cnt[BATCH];
__device__ unsigned long long g_cand  [BATCH * CAP];
__device__ unsigned long long g_sorted[BATCH * CAP];
__device__ int                g_segoff[BATCH + 1] =
    {0, CAP, 2*CAP, 3*CAP, 4*CAP, 5*CAP, 6*CAP, 7*CAP, 8*CAP};
__device__ __align__(16) float g_boxes[BATCH * TOPK * 4];
__device__ unsigned char      g_temp[16 * 1024 * 1024];             // cub temp

// -------- 1. per-batch histogram of score buckets ----------------------------
__global__ void hist_kernel(const float2* __restrict__ cls) {
    int g = blockIdx.x * blockDim.x + threadIdx.x;
    if (g >= TOTAL) return;
    float s = cls[g].y;                      // rpn_class[:,:,1], softmax > 0
    int bucket = (int)(__float_as_uint(s) >> 15);
    atomicAdd(&g_hist[(g >> 18) * HBINS + bucket], 1);
}

// -------- 2. threshold bucket: largest T with count(bucket >= T) >= TOPK -----
__global__ void thresh_kernel() {
    constexpr int BPT = HBINS / 256;
    int b = blockIdx.x;
    int t = threadIdx.x;
    __shared__ int lsum[256];
    __shared__ int suff[256];
    int base = b * HBINS + t * BPT;
    int s = 0;
    for (int i = 0; i < BPT; ++i) s += g_hist[base + i];
    lsum[t] = s;
    __syncthreads();
    if (t == 0) {
        int run = 0;
        for (int u = 255; u >= 0; --u) { suff[u] = run; run += lsum[u]; }
    }
    __syncthreads();
    int above = suff[t];
    if (above < TOPK && above + lsum[t] >= TOPK) {
        int run = above;
        for (int i = BPT - 1; i >= 0; --i) {
            run += g_hist[base + i];
            if (run >= TOPK) { g_thresh[b] = t * BPT + i; break; }
        }
    }
}

// -------- 3. compact candidates with composite key ----------------------------
// key = (score_bits << 18) | (0x3FFFF - idx): descending sort => desc by score,
// ties broken by ascending index == jax.lax.top_k semantics.
__global__ void compact_kernel(const float2* __restrict__ cls) {
    int g = blockIdx.x * blockDim.x + threadIdx.x;
    if (g >= TOTAL) return;
    unsigned int bits = __float_as_uint(cls[g].y);
    int b = g >> 18;
    if ((int)(bits >> 15) >= __ldg(&g_thresh[b])) {
        int pos = atomicAdd(&g_cnt[b], 1);
        if (pos < CAP)
            g_cand[b * CAP + pos] =
                ((unsigned long long)bits << 18) |
                (unsigned long long)(0x3FFFF - (g & (NANCH - 1)));
    }
}

// -------- 4. gather top-6000, apply deltas, clip ------------------------------
__global__ void boxes_kernel(const float* __restrict__ rpn_bbox,
                             const float* __restrict__ anchors) {
    int t = blockIdx.x * blockDim.x + threadIdx.x;
    if (t >= BATCH * TOPK) return;
    int b = t / TOPK;
    int k = t - b * TOPK;
    unsigned long long key = g_sorted[b * CAP + k];
    int idx = 0x3FFFF - (int)(key & 0x3FFFFull);
    int src = (b * NANCH + idx) * 4;
    float4 a = *reinterpret_cast<const float4*>(anchors  + src);
    float4 d = *reinterpret_cast<const float4*>(rpn_bbox + src);
    float dy = d.x * 0.1f, dx = d.y * 0.1f;
    float dh = d.z * 0.2f, dw = d.w * 0.2f;
    float h = a.z - a.x;
    float w = a.w - a.y;
    float cy = a.x + 0.5f * h;
    float cx = a.y + 0.5f * w;
    cy = cy + dy * h;
    cx = cx + dx * w;
    h = h * expf(dh);
    w = w * expf(dw);
    float y1 = fminf(fmaxf(cy - 0.5f * h, 0.f), 1.f);
    float x1 = fminf(fmaxf(cx - 0.5f * w, 0.f), 1.f);
    float y2 = fminf(fmaxf(cy + 0.5f * h, 0.f), 1.f);
    float x2 = fminf(fmaxf(cx + 0.5f * w, 0.f), 1.f);
    reinterpret_cast<float4*>(g_boxes)[t] = make_float4(y1, x1, y2, x2);
}

// -------- 5. fully fused NMS: lazy suppression, everything in smem -------------
// One block per batch. Per 64-bit word: (A) 64x64 diag IoU block for alive rows
// (parallel), (B) thread-0 keep chain in smem, (C) block-parallel suppression of
// alive later boxes vs this word's kept boxes. Only ~kept x alive pairs are ever
// evaluated (vs all-pairs precompute).
__global__ void __launch_bounds__(FTHREADS)
fused_nms_kernel(float* __restrict__ out) {
    extern __shared__ float4 sm4[];
    float4* boxes_sh = sm4;                                               // TOPK
    unsigned long long* alive_sh =
        reinterpret_cast<unsigned long long*>(boxes_sh + TOPK);           // COLB
    unsigned long long* diag_sh = alive_sh + COLB;                        // 64
    unsigned char* diagb = reinterpret_cast<unsigned char*>(diag_sh + 64);// 512
    int* kept_sh = reinterpret_cast<int*>(diagb + 512);                   // NOUT
    int* ctrl    = kept_sh + NOUT;

    int b = blockIdx.x;
    int tid = threadIdx.x;
    int lane = tid & 31;

    for (int i = tid; i < TOPK; i += FTHREADS)
        boxes_sh[i] = reinterpret_cast<const float4*>(g_boxes)[b * TOPK + i];
    if (tid < COLB)
        alive_sh[tid] = (tid == COLB - 1) ? ((1ull << TAIL_BITS) - 1ull) : ~0ull;
    __syncthreads();

    int cnt = 0;
    for (int w = 0; w < COLB; ++w) {
        unsigned long long aw = alive_sh[w];   // consistent: synced last iter
        if (aw == 0ull) continue;              // uniform branch

        // (A) diag block: rows split 64 x 8-col chunks over 512 threads.
        // Bits only needed where row AND col are alive; others may be 0.
        if (tid < 512) {
            int r  = tid >> 3;
            int ch = tid & 7;
            int gi = (w << 6) + r;
            unsigned byte = 0;
            if (gi < TOPK && ((aw >> r) & 1ull)) {
                float4 rb = boxes_sh[gi];
                float area1 = (rb.z - rb.x) * (rb.w - rb.y);
                #pragma unroll
                for (int k = 0; k < 8; ++k) {
                    int c  = (ch << 3) + k;
                    int gj = (w << 6) + c;
                    if (c > r && gj < TOPK && ((aw >> c) & 1ull)) {
                        float4 cb = boxes_sh[gj];
                        float y1 = fmaxf(rb.x, cb.x);
                        float x1 = fmaxf(rb.y, cb.y);
                        float y2 = fminf(rb.z, cb.z);
                        float x2 = fminf(rb.w, cb.w);
                        float ddy = y2 - y1, ddx = x2 - x1;
                        if (ddy > 0.f && ddx > 0.f) {
                            float inter = ddy * ddx;
                            float area2 = (cb.z - cb.x) * (cb.w - cb.y);
                            float iou = inter / (area1 + area2 - inter + 1e-9f);
                            if (iou > THR) byte |= 1u << k;
                        }
                    }
                }
            }
            diagb[tid] = (unsigned char)byte;
        }
        __syncthreads();
        if (tid < 64)
            diag_sh[tid] = reinterpret_cast<const unsigned long long*>(diagb)[tid];
        __syncthreads();

        // (B) keep chain for word w — smem only, thread 0.
        if (tid == 0) {
            unsigned long long avail = aw;
            int m = 0;
            while (avail && cnt + m < NOUT) {
                int bit = __ffsll((long long)avail) - 1;
                kept_sh[cnt + m] = (w << 6) + bit;
                ++m;
                avail &= avail - 1;        // clear taken bit (zero-area safe)
                avail &= ~diag_sh[bit];    // within-word forward suppression
            }
            ctrl[0] = m;
        }
        __syncthreads();
        int m = ctrl[0];

        // (C) suppress alive later boxes vs the m kept boxes of this word.
        // Benign race: concurrent clears within this phase only cause identical
        // recomputation; words are fenced by the loop-end __syncthreads.
        if (m > 0) {
            for (int jb = (w + 1) << 6; jb < TOPK; jb += FTHREADS) {
                int j = jb + tid;
                bool sup = false;
                if (j < TOPK && ((alive_sh[j >> 6] >> (j & 63)) & 1ull)) {
                    float4 bj = boxes_sh[j];
                    float areaj = (bj.z - bj.x) * (bj.w - bj.y);
                    for (int k = 0; k < m; ++k) {
                        float4 bk = boxes_sh[kept_sh[cnt + k]];
                        float y1 = fmaxf(bk.x, bj.x);
                        float x1 = fmaxf(bk.y, bj.y);
                        float y2 = fminf(bk.z, bj.z);
                        float x2 = fminf(bk.w, bj.w);
                        float ddy = y2 - y1, ddx = x2 - x1;
                        if (ddy > 0.f && ddx > 0.f) {
                            float inter = ddy * ddx;
                            float areak = (bk.z - bk.x) * (bk.w - bk.y);
                            float iou = inter / (areak + areaj - inter + 1e-9f);
                            if (iou > THR) { sup = true; break; }
                        }
                    }
                }
                unsigned bal = __ballot_sync(0xffffffffu, sup);
                if (lane == 0 && bal) {
                    int j0 = jb + (tid & ~31);   // warp's first j; 32-aligned
                    atomicAnd(&alive_sh[j0 >> 6],
                              ~((unsigned long long)bal << (j0 & 63)));
                }
            }
        }
        cnt += m;                 // uniform
        if (cnt >= NOUT) break;   // uniform
        __syncthreads();
    }
    __syncthreads();

    for (int k = tid; k < NOUT; k += FTHREADS) {
        float4 v = make_float4(0.f, 0.f, 0.f, 0.f);
        if (k < cnt) v = boxes_sh[kept_sh[k]];
        reinterpret_cast<float4*>(out)[b * NOUT + k] = v;
    }
}

// -------- launch --------------------------------------------------------------
extern "C" void kernel_launch(void* const* d_in, const int* in_sizes, int n_in,
                              void* d_out, int out_size) {
    const float* rpn_class = (const float*)d_in[0];
    const float* rpn_bbox  = (const float*)d_in[1];
    const float* anchors   = (const float*)d_in[2];
    float* out = (float*)d_out;

    void *histp, *cntp, *candp, *sortedp, *offp, *tmpp;
    cudaGetSymbolAddress(&histp,   g_hist);
    cudaGetSymbolAddress(&cntp,    g_cnt);
    cudaGetSymbolAddress(&candp,   g_cand);
    cudaGetSymbolAddress(&sortedp, g_sorted);
    cudaGetSymbolAddress(&offp,    g_segoff);
    cudaGetSymbolAddress(&tmpp,    g_temp);

    cudaMemsetAsync(histp, 0, sizeof(g_hist));
    cudaMemsetAsync(cntp,  0, sizeof(g_cnt));
    cudaMemsetAsync(candp, 0, sizeof(g_cand));   // zero keys sort to segment end

    hist_kernel<<<TOTAL / 256, 256>>>((const float2*)rpn_class);
    thresh_kernel<<<BATCH, 256>>>();
    compact_kernel<<<TOTAL / 256, 256>>>((const float2*)rpn_class);

    size_t temp_bytes = 0;
    cub::DeviceSegmentedRadixSort::SortKeysDescending(
        nullptr, temp_bytes,
        (const unsigned long long*)candp, (unsigned long long*)sortedp,
        BATCH * CAP, BATCH,
        (const int*)offp, ((const int*)offp) + 1, 0, 48);
    if (temp_bytes <= sizeof(g_temp)) {
        cub::DeviceSegmentedRadixSort::SortKeysDescending(
            tmpp, temp_bytes,
            (const unsigned long long*)candp, (unsigned long long*)sortedp,
            BATCH * CAP, BATCH,
            (const int*)offp, ((const int*)offp) + 1, 0, 48);
    }

    boxes_kernel<<<(BATCH * TOPK + 255) / 256, 256>>>(rpn_bbox, anchors);

    cudaFuncSetAttribute(fused_nms_kernel,
                         cudaFuncAttributeMaxDynamicSharedMemorySize, FUSED_SMEM);
    fused_nms_kernel<<<BATCH, FTHREADS, FUSED_SMEM>>>(out);
}

// round 9
// speedup vs baseline: 2.6086x; 2.6086x over previous
#include <cuda_runtime.h>
#include <cub/cub.cuh>
#include <cstdint>

namespace {
constexpr int BATCH = 8;
constexpr int NANCH = 262144;         // 2^18
constexpr int TOTAL = BATCH * NANCH;  // 2,097,152
constexpr int TOPK  = 6000;
constexpr int NOUT  = 1000;
constexpr int COLB  = (TOPK + 63) / 64;            // 94
constexpr float THR = 0.7f;
constexpr int TAIL_BITS = TOPK - (COLB - 1) * 64;  // 48
constexpr int HBINS = 32768;   // bucket = float_bits >> 15 (scores in (0,1))
constexpr int CAP   = 16384;   // per-batch candidate capacity (expected ~6400)
constexpr int NKEYS = BATCH * CAP;                  // 131072
constexpr int SWEEP_THREADS = 512;
constexpr int SWEEP_SMEM = TOPK * 8 + COLB * 8 + NOUT * 4 + 16;
}

// -------- device-global scratch (no allocation allowed) ----------------------
__device__ int                g_hist[BATCH * HBINS];
__device__ int                g_thresh[BATCH];
__device__ int                g_cnt[BATCH];
__device__ unsigned long long g_cand  [NKEYS];
__device__ unsigned long long g_sorted[NKEYS];
__device__ __align__(16) float g_boxes[BATCH * TOPK * 4];
__device__ unsigned long long g_mask[(size_t)BATCH * TOPK * COLB];  // upper-tri valid
__device__ unsigned long long g_diag[BATCH * TOPK];
__device__ unsigned char      g_temp[16 * 1024 * 1024];             // cub temp

// -------- 0. init candidate slots + clear counters (replaces memsets) --------
// Padding key = (7-b)<<48 : sorts to the TAIL of its own batch region under a
// global descending sort (real keys have score bits > 0 in [18,48)).
__global__ void init_kernel() {
    int g = blockIdx.x * blockDim.x + threadIdx.x;
    if (g < NKEYS) {
        int b = g / CAP;
        g_cand[g] = (unsigned long long)(7 - b) << 48;
    }
    if (g < BATCH) g_cnt[g] = 0;
    if (g < BATCH * HBINS) g_hist[g] = 0;
}

// -------- 1. per-batch histogram of score buckets ----------------------------
__global__ void hist_kernel(const float2* __restrict__ cls) {
    int g = blockIdx.x * blockDim.x + threadIdx.x;
    if (g >= TOTAL) return;
    float s = cls[g].y;                      // rpn_class[:,:,1], softmax > 0
    int bucket = (int)(__float_as_uint(s) >> 15);
    atomicAdd(&g_hist[(g >> 18) * HBINS + bucket], 1);
}

// -------- 2. threshold bucket: largest T with count(bucket >= T) >= TOPK -----
__global__ void thresh_kernel() {
    constexpr int BPT = HBINS / 256;
    int b = blockIdx.x;
    int t = threadIdx.x;
    __shared__ int lsum[256];
    __shared__ int suff[256];
    int base = b * HBINS + t * BPT;
    int s = 0;
    for (int i = 0; i < BPT; ++i) s += g_hist[base + i];
    lsum[t] = s;
    __syncthreads();
    if (t == 0) {
        int run = 0;
        for (int u = 255; u >= 0; --u) { suff[u] = run; run += lsum[u]; }
    }
    __syncthreads();
    int above = suff[t];
    if (above < TOPK && above + lsum[t] >= TOPK) {
        int run = above;
        for (int i = BPT - 1; i >= 0; --i) {
            run += g_hist[base + i];
            if (run >= TOPK) { g_thresh[b] = t * BPT + i; break; }
        }
    }
}

// -------- 3. compact candidates with composite 51-bit key ---------------------
// key = (7-b)<<48 | score_bits<<18 | (0x3FFFF - idx).
// Global descending sort => batch-0 region first, within batch: desc score,
// ties by ascending index == jax.lax.top_k semantics exactly.
__global__ void compact_kernel(const float2* __restrict__ cls) {
    int g = blockIdx.x * blockDim.x + threadIdx.x;
    if (g >= TOTAL) return;
    unsigned int bits = __float_as_uint(cls[g].y);
    int b = g >> 18;
    if ((int)(bits >> 15) >= __ldg(&g_thresh[b])) {
        int pos = atomicAdd(&g_cnt[b], 1);
        if (pos < CAP)
            g_cand[b * CAP + pos] =
                ((unsigned long long)(7 - b) << 48) |
                ((unsigned long long)bits << 18) |
                (unsigned long long)(0x3FFFF - (g & (NANCH - 1)));
    }
}

// -------- 4. gather top-6000, apply deltas, clip ------------------------------
__global__ void boxes_kernel(const float* __restrict__ rpn_bbox,
                             const float* __restrict__ anchors) {
    int t = blockIdx.x * blockDim.x + threadIdx.x;
    if (t >= BATCH * TOPK) return;
    int b = t / TOPK;
    int k = t - b * TOPK;
    unsigned long long key = g_sorted[b * CAP + k];
    int idx = 0x3FFFF - (int)(key & 0x3FFFFull);
    int src = (b * NANCH + idx) * 4;
    float4 a = *reinterpret_cast<const float4*>(anchors  + src);
    float4 d = *reinterpret_cast<const float4*>(rpn_bbox + src);
    float dy = d.x * 0.1f, dx = d.y * 0.1f;
    float dh = d.z * 0.2f, dw = d.w * 0.2f;
    float h = a.z - a.x;
    float w = a.w - a.y;
    float cy = a.x + 0.5f * h;
    float cx = a.y + 0.5f * w;
    cy = cy + dy * h;
    cx = cx + dx * w;
    h = h * expf(dh);
    w = w * expf(dw);
    float y1 = fminf(fmaxf(cy - 0.5f * h, 0.f), 1.f);
    float x1 = fminf(fmaxf(cx - 0.5f * w, 0.f), 1.f);
    float y2 = fminf(fmaxf(cy + 0.5f * h, 0.f), 1.f);
    float x2 = fminf(fmaxf(cx + 0.5f * w, 0.f), 1.f);
    reinterpret_cast<float4*>(g_boxes)[t] = make_float4(y1, x1, y2, x2);
}

// -------- 5. pairwise IoU bitmask — upper triangle, unrolled 2-pass ------------
// Pass 1 (fully unrolled, compile-time bit positions -> predicated LOP3):
// separating-axis test per col, candidate mask in two 32-bit halves. Exact:
// no overlap => inter == 0 => iou == 0 < THR. Pass 2: exact fp32 IoU only on
// candidate bits (~10%).
__global__ void iou_kernel() {
    int b = blockIdx.z;
    int C = blockIdx.x * 64;           // column start
    int R = blockIdx.y * 256;          // row start
    if (R >= C + 64) return;           // whole block below diagonal: never read
    __shared__ float4 colBox[64];
    int tid = threadIdx.x;
    int ncols = min(64, TOPK - C);
    if (tid < ncols)
        colBox[tid] = reinterpret_cast<const float4*>(g_boxes)[b * TOPK + C + tid];
    __syncthreads();
    int i = R + tid;
    if (i >= TOPK || i >= C + 64) return;
    float4 rb = reinterpret_cast<const float4*>(g_boxes)[b * TOPK + i];
    float area1 = (rb.z - rb.x) * (rb.w - rb.y);

    unsigned mlo = 0, mhi = 0;
    if (ncols == 64) {
        #pragma unroll
        for (int j = 0; j < 64; ++j) {
            float4 cb = colBox[j];
            float ddy = fminf(rb.z, cb.z) - fmaxf(rb.x, cb.x);
            float ddx = fminf(rb.w, cb.w) - fmaxf(rb.y, cb.y);
            bool ov = (ddy > 0.f) && (ddx > 0.f);
            if (j < 32) mlo |= ov ? (1u << j) : 0u;
            else        mhi |= ov ? (1u << (j - 32)) : 0u;
        }
    } else {
        for (int j = 0; j < ncols; ++j) {
            float4 cb = colBox[j];
            float ddy = fminf(rb.z, cb.z) - fmaxf(rb.x, cb.x);
            float ddx = fminf(rb.w, cb.w) - fmaxf(rb.y, cb.y);
            bool ov = (ddy > 0.f) && (ddx > 0.f);
            if (j < 32) mlo |= ov ? (1u << j) : 0u;
            else        mhi |= ov ? (1u << (j - 32)) : 0u;
        }
    }

    unsigned long long cand = ((unsigned long long)mhi << 32) | mlo;
    unsigned long long m = 0;
    while (cand) {
        int j = __ffsll((long long)cand) - 1;
        cand &= cand - 1;
        float4 cb = colBox[j];
        float y1 = fmaxf(rb.x, cb.x);
        float x1 = fmaxf(rb.y, cb.y);
        float y2 = fminf(rb.z, cb.z);
        float x2 = fminf(rb.w, cb.w);
        float inter = fmaxf(y2 - y1, 0.f) * fmaxf(x2 - x1, 0.f);
        float area2 = (cb.z - cb.x) * (cb.w - cb.y);
        float iou = inter / (area1 + area2 - inter + 1e-9f);
        if (iou > THR) m |= 1ull << j;
    }
    g_mask[((size_t)(b * TOPK + i)) * COLB + blockIdx.x] = m;
    if ((i >> 6) == (C >> 6))
        g_diag[b * TOPK + i] = m;          // row i's own word, for the fast chain
}

// -------- 6. sweep: smem chain (thread 0) + block-parallel batched row ORs -----
__global__ void __launch_bounds__(SWEEP_THREADS)
sweep_kernel(float* __restrict__ out) {
    extern __shared__ unsigned long long dsm[];
    unsigned long long* diag_sh = dsm;                 // TOPK u64 (48 KB)
    unsigned long long* rem_sh  = dsm + TOPK;          // COLB u64
    int* kept_sh = reinterpret_cast<int*>(rem_sh + COLB);  // NOUT ints
    int* ctrl    = kept_sh + NOUT;                     // [0]=m for this word

    int b = blockIdx.x;
    int tid = threadIdx.x;
    int warp = tid >> 5;
    int lane = tid & 31;
    constexpr int NWARP = SWEEP_THREADS / 32;

    for (int i = tid; i < TOPK; i += SWEEP_THREADS)
        diag_sh[i] = g_diag[b * TOPK + i];
    if (tid < COLB)
        rem_sh[tid] = (tid == COLB - 1) ? ~((1ull << TAIL_BITS) - 1ull) : 0ull;
    __syncthreads();

    int cnt = 0;
    for (int w = 0; w < COLB; ++w) {
        // Phase A (thread 0): resolve all kept bits of word w using smem only.
        if (tid == 0) {
            unsigned long long avail = ~rem_sh[w];
            int m = 0;
            while (avail && cnt + m < NOUT) {
                int bit = __ffsll((long long)avail) - 1;
                int i = (w << 6) + bit;
                kept_sh[cnt + m] = i;
                ++m;
                avail &= avail - 1;        // clear taken bit (zero-area safe)
                avail &= ~diag_sh[i];      // within-word forward suppression
            }
            ctrl[0] = m;
        }
        __syncthreads();
        int m = ctrl[0];
        // Phase B (whole block): OR the m kept rows into rem for words > w.
        // 16 warps split k -> one round; lanes split ww -> independent LDGs.
        for (int k = warp; k < m; k += NWARP) {
            const unsigned long long* row =
                &g_mask[((size_t)(b * TOPK + kept_sh[cnt + k])) * COLB];
            for (int ww = w + 1 + lane; ww < COLB; ww += 32)
                atomicOr(&rem_sh[ww], row[ww]);
        }
        cnt += m;
        if (cnt >= NOUT) break;           // uniform across block: safe
        __syncthreads();
    }
    __syncthreads();

    for (int k = tid; k < NOUT; k += SWEEP_THREADS) {
        float4 v = make_float4(0.f, 0.f, 0.f, 0.f);
        if (k < cnt)
            v = reinterpret_cast<const float4*>(g_boxes)[b * TOPK + kept_sh[k]];
        reinterpret_cast<float4*>(out)[b * NOUT + k] = v;
    }
}

// -------- launch --------------------------------------------------------------
extern "C" void kernel_launch(void* const* d_in, const int* in_sizes, int n_in,
                              void* d_out, int out_size) {
    const float* rpn_class = (const float*)d_in[0];
    const float* rpn_bbox  = (const float*)d_in[1];
    const float* anchors   = (const float*)d_in[2];
    float* out = (float*)d_out;

    void *candp, *sortedp, *tmpp;
    cudaGetSymbolAddress(&candp,   g_cand);
    cudaGetSymbolAddress(&sortedp, g_sorted);
    cudaGetSymbolAddress(&tmpp,    g_temp);

    init_kernel<<<(BATCH * HBINS + 255) / 256, 256>>>();
    hist_kernel<<<TOTAL / 256, 256>>>((const float2*)rpn_class);
    thresh_kernel<<<BATCH, 256>>>();
    compact_kernel<<<TOTAL / 256, 256>>>((const float2*)rpn_class);

    // Global descending radix sort over all batches at once (51-bit keys).
    size_t temp_bytes = 0;
    cub::DeviceRadixSort::SortKeysDescending(
        nullptr, temp_bytes,
        (const unsigned long long*)candp, (unsigned long long*)sortedp,
        NKEYS, 0, 51);
    if (temp_bytes <= sizeof(g_temp)) {
        cub::DeviceRadixSort::SortKeysDescending(
            tmpp, temp_bytes,
            (const unsigned long long*)candp, (unsigned long long*)sortedp,
            NKEYS, 0, 51);
    }

    boxes_kernel<<<(BATCH * TOPK + 255) / 256, 256>>>(rpn_bbox, anchors);

    dim3 gmask(COLB, (TOPK + 255) / 256, BATCH);
    iou_kernel<<<gmask, 256>>>();

    cudaFuncSetAttribute(sweep_kernel,
                         cudaFuncAttributeMaxDynamicSharedMemorySize, SWEEP_SMEM);
    sweep_kernel<<<BATCH, SWEEP_THREADS, SWEEP_SMEM>>>(out);
}

// round 11
// speedup vs baseline: 2.6676x; 1.0226x over previous
#include <cuda_runtime.h>
#include <cub/cub.cuh>
#include <cstdint>

namespace {
constexpr int BATCH = 8;
constexpr int NANCH = 262144;         // 2^18
constexpr int TOTAL = BATCH * NANCH;  // 2,097,152
constexpr int TOPK  = 6000;
constexpr int NOUT  = 1000;
constexpr int COLB  = (TOPK + 63) / 64;            // 94
constexpr float THR = 0.7f;
constexpr int TAIL_BITS = TOPK - (COLB - 1) * 64;  // 48
constexpr int HBINS = 32768;   // bucket = float_bits >> 15 (scores in (0,1))
constexpr int CAP   = 16384;   // per-batch candidate capacity (expected ~6400)
constexpr int SORT_THREADS = 1024;
constexpr int SORT_ITEMS   = CAP / SORT_THREADS;   // 16
constexpr int SWEEP_THREADS = 512;
constexpr int SWEEP_SMEM = TOPK * 8 + COLB * 8 + NOUT * 4 + 16;
constexpr int IOU_ROWS = 512;          // rows per iou block (2 per thread)
}

// -------- device-global scratch (no allocation allowed) ----------------------
__device__ int                g_hist[BATCH * HBINS];
__device__ int                g_thresh[BATCH];
__device__ int                g_cnt[BATCH];
__device__ unsigned long long g_cand  [BATCH * CAP];
__device__ unsigned long long g_sorted[BATCH * CAP];
__device__ __align__(16) float g_boxes[BATCH * TOPK * 4];
__device__ unsigned long long g_mask[(size_t)BATCH * TOPK * COLB];  // upper-tri valid
__device__ unsigned long long g_diag[BATCH * TOPK];

// -------- 1. per-batch histogram — 4 elements/thread (MLP=2) ------------------
__global__ void hist_kernel(const float4* __restrict__ cls4) {
    int t = blockIdx.x * blockDim.x + threadIdx.x;
    int e0 = t << 2;                         // 4 elements; never crosses a batch
    if (e0 >= TOTAL) return;
    float4 v0 = __ldg(&cls4[t * 2]);
    float4 v1 = __ldg(&cls4[t * 2 + 1]);     // scores at .y / .w (rpn_class[...,1])
    int* h = &g_hist[(e0 >> 18) * HBINS];
    atomicAdd(&h[__float_as_uint(v0.y) >> 15], 1);
    atomicAdd(&h[__float_as_uint(v0.w) >> 15], 1);
    atomicAdd(&h[__float_as_uint(v1.y) >> 15], 1);
    atomicAdd(&h[__float_as_uint(v1.w) >> 15], 1);
}

// -------- 2. threshold bucket: largest T with count(bucket >= T) >= TOPK -----
__global__ void thresh_kernel() {
    constexpr int BPT = HBINS / 256;
    int b = blockIdx.x;
    int t = threadIdx.x;
    __shared__ int lsum[256];
    __shared__ int suff[256];
    int base = b * HBINS + t * BPT;
    int s = 0;
    for (int i = 0; i < BPT; ++i) s += g_hist[base + i];
    lsum[t] = s;
    __syncthreads();
    if (t == 0) {
        int run = 0;
        for (int u = 255; u >= 0; --u) { suff[u] = run; run += lsum[u]; }
    }
    __syncthreads();
    int above = suff[t];
    if (above < TOPK && above + lsum[t] >= TOPK) {
        int run = above;
        for (int i = BPT - 1; i >= 0; --i) {
            run += g_hist[base + i];
            if (run >= TOPK) { g_thresh[b] = t * BPT + i; break; }
        }
    }
}

// -------- 3. compact candidates — 4 elements/thread, 48-bit keys --------------
// key = score_bits<<18 | (0x3FFFF - idx). Per-batch descending sort => desc
// score, ties by ascending index == jax.lax.top_k semantics exactly.
__global__ void compact_kernel(const float4* __restrict__ cls4) {
    int t = blockIdx.x * blockDim.x + threadIdx.x;
    int e0 = t << 2;
    if (e0 >= TOTAL) return;
    float4 v0 = __ldg(&cls4[t * 2]);
    float4 v1 = __ldg(&cls4[t * 2 + 1]);
    int b = e0 >> 18;
    int T = __ldg(&g_thresh[b]);
    unsigned sc[4] = { __float_as_uint(v0.y), __float_as_uint(v0.w),
                       __float_as_uint(v1.y), __float_as_uint(v1.w) };
    #pragma unroll
    for (int i = 0; i < 4; ++i) {
        if ((int)(sc[i] >> 15) >= T) {
            int pos = atomicAdd(&g_cnt[b], 1);
            if (pos < CAP)
                g_cand[b * CAP + pos] =
                    ((unsigned long long)sc[i] << 18) |
                    (unsigned long long)(0x3FFFF - ((e0 + i) & (NANCH - 1)));
        }
    }
}

// -------- 3b. per-batch in-smem radix sort (replaces device radix sort) -------
using BlockSortT = cub::BlockRadixSort<unsigned long long, SORT_THREADS, SORT_ITEMS>;
__global__ void __launch_bounds__(SORT_THREADS)
sort_kernel() {
    extern __shared__ char sort_raw[];
    auto& ts = *reinterpret_cast<typename BlockSortT::TempStorage*>(sort_raw);
    int b = blockIdx.x;
    int cnt = min(g_cnt[b], CAP);
    unsigned long long keys[SORT_ITEMS];
    #pragma unroll
    for (int k = 0; k < SORT_ITEMS; ++k) {
        int i = threadIdx.x * SORT_ITEMS + k;      // blocked arrangement
        keys[k] = (i < cnt) ? g_cand[b * CAP + i] : 0ull;  // 0 pads to tail
    }
    BlockSortT(ts).SortDescending(keys, 0, 48);
    #pragma unroll
    for (int k = 0; k < SORT_ITEMS; ++k) {
        int i = threadIdx.x * SORT_ITEMS + k;
        if (i < TOPK) g_sorted[b * CAP + i] = keys[k];
    }
}

// -------- 4. gather top-6000, apply deltas, clip ------------------------------
__global__ void boxes_kernel(const float* __restrict__ rpn_bbox,
                             const float* __restrict__ anchors) {
    int t = blockIdx.x * blockDim.x + threadIdx.x;
    if (t >= BATCH * TOPK) return;
    int b = t / TOPK;
    int k = t - b * TOPK;
    unsigned long long key = g_sorted[b * CAP + k];
    int idx = 0x3FFFF - (int)(key & 0x3FFFFull);
    int src = (b * NANCH + idx) * 4;
    float4 a = *reinterpret_cast<const float4*>(anchors  + src);
    float4 d = *reinterpret_cast<const float4*>(rpn_bbox + src);
    float dy = d.x * 0.1f, dx = d.y * 0.1f;
    float dh = d.z * 0.2f, dw = d.w * 0.2f;
    float h = a.z - a.x;
    float w = a.w - a.y;
    float cy = a.x + 0.5f * h;
    float cx = a.y + 0.5f * w;
    cy = cy + dy * h;
    cx = cx + dx * w;
    h = h * expf(dh);
    w = w * expf(dw);
    float y1 = fminf(fmaxf(cy - 0.5f * h, 0.f), 1.f);
    float x1 = fminf(fmaxf(cx - 0.5f * w, 0.f), 1.f);
    float y2 = fminf(fmaxf(cy + 0.5f * h, 0.f), 1.f);
    float x2 = fminf(fmaxf(cx + 0.5f * w, 0.f), 1.f);
    reinterpret_cast<float4*>(g_boxes)[t] = make_float4(y1, x1, y2, x2);
}

// -------- 5. pairwise IoU bitmask — upper triangle, 2 rows/thread --------------
// Each colBox LDS serves two rows (halves smem traffic). Pass 1: unrolled
// separating-axis test (exact filter). Pass 2: exact fp32 IoU on candidates.
__device__ __forceinline__ void iou_row(
    const float4* colBox, float4 rb, int ncols, unsigned long long cand,
    unsigned long long* maskOut, unsigned long long* diagOut) {
    float area1 = (rb.z - rb.x) * (rb.w - rb.y);
    unsigned long long m = 0;
    while (cand) {
        int j = __ffsll((long long)cand) - 1;
        cand &= cand - 1;
        float4 cb = colBox[j];
        float y1 = fmaxf(rb.x, cb.x);
        float x1 = fmaxf(rb.y, cb.y);
        float y2 = fminf(rb.z, cb.z);
        float x2 = fminf(rb.w, cb.w);
        float inter = fmaxf(y2 - y1, 0.f) * fmaxf(x2 - x1, 0.f);
        float area2 = (cb.z - cb.x) * (cb.w - cb.y);
        float iou = inter / (area1 + area2 - inter + 1e-9f);
        if (iou > THR) m |= 1ull << j;
    }
    *maskOut = m;
    if (diagOut) *diagOut = m;
}

__global__ void iou_kernel() {
    int b = blockIdx.z;
    int C = blockIdx.x * 64;                 // column start
    int R = blockIdx.y * IOU_ROWS;           // row start
    if (R >= C + 64) return;                 // block fully below diagonal
    __shared__ float4 colBox[64];
    int tid = threadIdx.x;
    int ncols = min(64, TOPK - C);
    if (tid < ncols)
        colBox[tid] = reinterpret_cast<const float4*>(g_boxes)[b * TOPK + C + tid];
    __syncthreads();

    int i0 = R + tid;
    int i1 = R + tid + 256;
    bool v0 = (i0 < TOPK) && (i0 < C + 64);
    bool v1 = (i1 < TOPK) && (i1 < C + 64);
    if (!v0 && !v1) return;
    float4 rb0 = v0 ? reinterpret_cast<const float4*>(g_boxes)[b * TOPK + i0]
                    : make_float4(0.f, 0.f, 0.f, 0.f);
    float4 rb1 = v1 ? reinterpret_cast<const float4*>(g_boxes)[b * TOPK + i1]
                    : make_float4(0.f, 0.f, 0.f, 0.f);

    unsigned lo0 = 0, hi0 = 0, lo1 = 0, hi1 = 0;
    if (ncols == 64) {
        #pragma unroll
        for (int j = 0; j < 64; ++j) {
            float4 cb = colBox[j];
            float a0 = fminf(rb0.z, cb.z) - fmaxf(rb0.x, cb.x);
            float b0 = fminf(rb0.w, cb.w) - fmaxf(rb0.y, cb.y);
            float a1 = fminf(rb1.z, cb.z) - fmaxf(rb1.x, cb.x);
            float b1 = fminf(rb1.w, cb.w) - fmaxf(rb1.y, cb.y);
            bool o0 = (a0 > 0.f) && (b0 > 0.f);
            bool o1 = (a1 > 0.f) && (b1 > 0.f);
            if (j < 32) { lo0 |= o0 ? (1u << j) : 0u;  lo1 |= o1 ? (1u << j) : 0u; }
            else        { hi0 |= o0 ? (1u << (j-32)) : 0u;  hi1 |= o1 ? (1u << (j-32)) : 0u; }
        }
    } else {
        for (int j = 0; j < ncols; ++j) {
            float4 cb = colBox[j];
            float a0 = fminf(rb0.z, cb.z) - fmaxf(rb0.x, cb.x);
            float b0 = fminf(rb0.w, cb.w) - fmaxf(rb0.y, cb.y);
            float a1 = fminf(rb1.z, cb.z) - fmaxf(rb1.x, cb.x);
            float b1 = fminf(rb1.w, cb.w) - fmaxf(rb1.y, cb.y);
            bool o0 = (a0 > 0.f) && (b0 > 0.f);
            bool o1 = (a1 > 0.f) && (b1 > 0.f);
            if (j < 32) { lo0 |= o0 ? (1u << j) : 0u;  lo1 |= o1 ? (1u << j) : 0u; }
            else        { hi0 |= o0 ? (1u << (j-32)) : 0u;  hi1 |= o1 ? (1u << (j-32)) : 0u; }
        }
    }

    if (v0) {
        bool isDiag = ((i0 >> 6) == (C >> 6));
        unsigned long long* dout = isDiag ? &g_diag[b * TOPK + i0] : nullptr;
        iou_row(colBox, rb0, ncols,
                ((unsigned long long)hi0 << 32) | lo0,
                &g_mask[((size_t)(b * TOPK + i0)) * COLB + blockIdx.x], dout);
    }
    if (v1) {
        bool isDiag = ((i1 >> 6) == (C >> 6));
        unsigned long long* dout = isDiag ? &g_diag[b * TOPK + i1] : nullptr;
        iou_row(colBox, rb1, ncols,
                ((unsigned long long)hi1 << 32) | lo1,
                &g_mask[((size_t)(b * TOPK + i1)) * COLB + blockIdx.x], dout);
    }
}

// -------- 6. sweep: smem chain (thread 0) + block-parallel batched row ORs -----
__global__ void __launch_bounds__(SWEEP_THREADS)
sweep_kernel(float* __restrict__ out) {
    extern __shared__ unsigned long long dsm[];
    unsigned long long* diag_sh = dsm;                 // TOPK u64 (48 KB)
    unsigned long long* rem_sh  = dsm + TOPK;          // COLB u64
    int* kept_sh = reinterpret_cast<int*>(rem_sh + COLB);  // NOUT ints
    int* ctrl    = kept_sh + NOUT;                     // [0]=m for this word

    int b = blockIdx.x;
    int tid = threadIdx.x;
    int warp = tid >> 5;
    int lane = tid & 31;
    constexpr int NWARP = SWEEP_THREADS / 32;

    for (int i = tid; i < TOPK; i += SWEEP_THREADS)
        diag_sh[i] = g_diag[b * TOPK + i];
    if (tid < COLB)
        rem_sh[tid] = (tid == COLB - 1) ? ~((1ull << TAIL_BITS) - 1ull) : 0ull;
    __syncthreads();

    int cnt = 0;
    for (int w = 0; w < COLB; ++w) {
        // Phase A (thread 0): resolve all kept bits of word w using smem only.
        if (tid == 0) {
            unsigned long long avail = ~rem_sh[w];
            int m = 0;
            while (avail && cnt + m < NOUT) {
                int bit = __ffsll((long long)avail) - 1;
                int i = (w << 6) + bit;
                kept_sh[cnt + m] = i;
                ++m;
                avail &= avail - 1;        // clear taken bit (zero-area safe)
                avail &= ~diag_sh[i];      // within-word forward suppression
            }
            ctrl[0] = m;
        }
        __syncthreads();
        int m = ctrl[0];
        // Phase B (whole block): OR the m kept rows into rem for words > w.
        for (int k = warp; k < m; k += NWARP) {
            const unsigned long long* row =
                &g_mask[((size_t)(b * TOPK + kept_sh[cnt + k])) * COLB];
            for (int ww = w + 1 + lane; ww < COLB; ww += 32)
                atomicOr(&rem_sh[ww], row[ww]);
        }
        cnt += m;
        if (cnt >= NOUT) break;           // uniform across block: safe
        __syncthreads();
    }
    __syncthreads();

    for (int k = tid; k < NOUT; k += SWEEP_THREADS) {
        float4 v = make_float4(0.f, 0.f, 0.f, 0.f);
        if (k < cnt)
            v = reinterpret_cast<const float4*>(g_boxes)[b * TOPK + kept_sh[k]];
        reinterpret_cast<float4*>(out)[b * NOUT + k] = v;
    }
}

// -------- launch --------------------------------------------------------------
extern "C" void kernel_launch(void* const* d_in, const int* in_sizes, int n_in,
                              void* d_out, int out_size) {
    const float* rpn_class = (const float*)d_in[0];
    const float* rpn_bbox  = (const float*)d_in[1];
    const float* anchors   = (const float*)d_in[2];
    float* out = (float*)d_out;

    void *histp, *cntp;
    cudaGetSymbolAddress(&histp, g_hist);
    cudaGetSymbolAddress(&cntp,  g_cnt);
    cudaMemsetAsync(histp, 0, sizeof(g_hist));
    cudaMemsetAsync(cntp,  0, sizeof(g_cnt));

    hist_kernel<<<TOTAL / 4 / 256, 256>>>((const float4*)rpn_class);
    thresh_kernel<<<BATCH, 256>>>();
    compact_kernel<<<TOTAL / 4 / 256, 256>>>((const float4*)rpn_class);

    constexpr int SORT_SMEM = (int)sizeof(typename BlockSortT::TempStorage);
    cudaFuncSetAttribute(sort_kernel,
                         cudaFuncAttributeMaxDynamicSharedMemorySize, SORT_SMEM);
    sort_kernel<<<BATCH, SORT_THREADS, SORT_SMEM>>>();

    boxes_kernel<<<(BATCH * TOPK + 255) / 256, 256>>>(rpn_bbox, anchors);

    dim3 gmask(COLB, (TOPK + IOU_ROWS - 1) / IOU_ROWS, BATCH);
    iou_kernel<<<gmask, 256>>>();

    cudaFuncSetAttribute(sweep_kernel,
                         cudaFuncAttributeMaxDynamicSharedMemorySize, SWEEP_SMEM);
    sweep_kernel<<<BATCH, SWEEP_THREADS, SWEEP_SMEM>>>(out);
}

// round 13
// speedup vs baseline: 2.8341x; 1.0624x over previous
#include <cuda_runtime.h>
#include <cub/cub.cuh>
#include <cstdint>

namespace {
constexpr int BATCH = 8;
constexpr int NANCH = 262144;         // 2^18
constexpr int TOTAL = BATCH * NANCH;  // 2,097,152
constexpr int TOPK  = 6000;
constexpr int NOUT  = 1000;
constexpr int COLB  = (TOPK + 63) / 64;            // 94
constexpr float THR = 0.7f;
constexpr int TAIL_BITS = TOPK - (COLB - 1) * 64;  // 48
constexpr int HBINS = 32768;   // bucket = float_bits >> 15 (scores in (0,1))
constexpr int CAP   = 10240;   // per-batch candidate capacity (expected ~6500)
constexpr int SORT_THREADS = 1024;
constexpr int SORT_ITEMS   = CAP / SORT_THREADS;   // 10
constexpr int SWEEP_THREADS = 512;
constexpr int SWEEP_SMEM = TOPK * 8 + COLB * 8 + NOUT * 4 + 16;
constexpr int IOU_ROWS = 1024;         // rows per iou block (4 per thread)
}

// -------- device-global scratch (no allocation allowed) ----------------------
__device__ int                g_hist[BATCH * HBINS];
__device__ int                g_thresh[BATCH];
__device__ int                g_cnt[BATCH];
__device__ unsigned long long g_cand  [BATCH * CAP];
__device__ unsigned long long g_sorted[BATCH * CAP];
__device__ __align__(16) float g_boxes[BATCH * TOPK * 4];
__device__ unsigned long long g_mask[(size_t)BATCH * TOPK * COLB];  // upper-tri valid
__device__ unsigned long long g_diag[BATCH * TOPK];

// -------- 1. per-batch histogram — 4 elements/thread (MLP=2) ------------------
__global__ void hist_kernel(const float4* __restrict__ cls4) {
    int t = blockIdx.x * blockDim.x + threadIdx.x;
    int e0 = t << 2;                         // 4 elements; never crosses a batch
    if (e0 >= TOTAL) return;
    float4 v0 = __ldg(&cls4[t * 2]);
    float4 v1 = __ldg(&cls4[t * 2 + 1]);     // scores at .y / .w (rpn_class[...,1])
    int* h = &g_hist[(e0 >> 18) * HBINS];
    atomicAdd(&h[__float_as_uint(v0.y) >> 15], 1);
    atomicAdd(&h[__float_as_uint(v0.w) >> 15], 1);
    atomicAdd(&h[__float_as_uint(v1.y) >> 15], 1);
    atomicAdd(&h[__float_as_uint(v1.w) >> 15], 1);
}

// -------- 2. threshold bucket: largest T with count(bucket >= T) >= TOPK -----
__global__ void thresh_kernel() {
    constexpr int BPT = HBINS / 256;
    int b = blockIdx.x;
    int t = threadIdx.x;
    __shared__ int lsum[256];
    __shared__ int suff[256];
    int base = b * HBINS + t * BPT;
    int s = 0;
    for (int i = 0; i < BPT; ++i) s += g_hist[base + i];
    lsum[t] = s;
    __syncthreads();
    if (t == 0) {
        int run = 0;
        for (int u = 255; u >= 0; --u) { suff[u] = run; run += lsum[u]; }
    }
    __syncthreads();
    int above = suff[t];
    if (above < TOPK && above + lsum[t] >= TOPK) {
        int run = above;
        for (int i = BPT - 1; i >= 0; --i) {
            run += g_hist[base + i];
            if (run >= TOPK) { g_thresh[b] = t * BPT + i; break; }
        }
    }
}

// -------- 3. compact candidates — threshold-rebased keys ----------------------
// key = (bits - T<<15) << 18 | (0x3FFFF - idx). Monotone shift of score bits:
// per-batch descending sort => desc score, ties by ascending index == top_k.
// Rebasing bounds keys to ~42 bits -> fewer radix passes (runtime end_bit).
__global__ void compact_kernel(const float4* __restrict__ cls4) {
    int t = blockIdx.x * blockDim.x + threadIdx.x;
    int e0 = t << 2;
    if (e0 >= TOTAL) return;
    float4 v0 = __ldg(&cls4[t * 2]);
    float4 v1 = __ldg(&cls4[t * 2 + 1]);
    int b = e0 >> 18;
    unsigned Tb = (unsigned)__ldg(&g_thresh[b]) << 15;
    unsigned sc[4] = { __float_as_uint(v0.y), __float_as_uint(v0.w),
                       __float_as_uint(v1.y), __float_as_uint(v1.w) };
    #pragma unroll
    for (int i = 0; i < 4; ++i) {
        if (sc[i] >= Tb) {
            int pos = atomicAdd(&g_cnt[b], 1);
            if (pos < CAP)
                g_cand[b * CAP + pos] =
                    ((unsigned long long)(sc[i] - Tb) << 18) |
                    (unsigned long long)(0x3FFFF - ((e0 + i) & (NANCH - 1)));
        }
    }
}

// -------- 3b. per-batch in-smem radix sort (runtime bit count) ----------------
using BlockSortT = cub::BlockRadixSort<unsigned long long, SORT_THREADS, SORT_ITEMS>;
__global__ void __launch_bounds__(SORT_THREADS)
sort_kernel() {
    extern __shared__ char sort_raw[];
    auto& ts = *reinterpret_cast<typename BlockSortT::TempStorage*>(sort_raw);
    int b = blockIdx.x;
    int cnt = min(g_cnt[b], CAP);
    int D = 32768 - g_thresh[b];         // rebased score' < D * 2^15
    int ebits = 33 + (32 - __clz(D | 1));  // 18 idx + 15 + bits(D)
    if (ebits > 48) ebits = 48;
    unsigned long long keys[SORT_ITEMS];
    #pragma unroll
    for (int k = 0; k < SORT_ITEMS; ++k) {
        int i = threadIdx.x * SORT_ITEMS + k;      // blocked arrangement
        keys[k] = (i < cnt) ? g_cand[b * CAP + i] : 0ull;  // 0 pads to tail
    }
    BlockSortT(ts).SortDescending(keys, 0, ebits);
    #pragma unroll
    for (int k = 0; k < SORT_ITEMS; ++k) {
        int i = threadIdx.x * SORT_ITEMS + k;
        if (i < TOPK) g_sorted[b * CAP + i] = keys[k];
    }
}

// -------- 4. gather top-6000, apply deltas, clip ------------------------------
__global__ void boxes_kernel(const float* __restrict__ rpn_bbox,
                             const float* __restrict__ anchors) {
    int t = blockIdx.x * blockDim.x + threadIdx.x;
    if (t >= BATCH * TOPK) return;
    int b = t / TOPK;
    int k = t - b * TOPK;
    unsigned long long key = g_sorted[b * CAP + k];
    int idx = 0x3FFFF - (int)(key & 0x3FFFFull);
    int src = (b * NANCH + idx) * 4;
    float4 a = *reinterpret_cast<const float4*>(anchors  + src);
    float4 d = *reinterpret_cast<const float4*>(rpn_bbox + src);
    float dy = d.x * 0.1f, dx = d.y * 0.1f;
    float dh = d.z * 0.2f, dw = d.w * 0.2f;
    float h = a.z - a.x;
    float w = a.w - a.y;
    float cy = a.x + 0.5f * h;
    float cx = a.y + 0.5f * w;
    cy = cy + dy * h;
    cx = cx + dx * w;
    h = h * expf(dh);
    w = w * expf(dw);
    float y1 = fminf(fmaxf(cy - 0.5f * h, 0.f), 1.f);
    float x1 = fminf(fmaxf(cx - 0.5f * w, 0.f), 1.f);
    float y2 = fminf(fmaxf(cy + 0.5f * h, 0.f), 1.f);
    float x2 = fminf(fmaxf(cx + 0.5f * w, 0.f), 1.f);
    reinterpret_cast<float4*>(g_boxes)[t] = make_float4(y1, x1, y2, x2);
}

// -------- 5. pairwise IoU bitmask — upper triangle, 4 rows/thread --------------
// One colBox LDS.128 feeds 4 rows -> smem traffic / 4. Pass 1: unrolled
// separating-axis test (exact filter: no overlap => iou == 0 < THR).
// Pass 2: exact fp32 IoU on candidate bits only.
__device__ __forceinline__ void iou_row(
    const float4* colBox, float4 rb, unsigned long long cand,
    unsigned long long* maskOut, unsigned long long* diagOut) {
    float area1 = (rb.z - rb.x) * (rb.w - rb.y);
    unsigned long long m = 0;
    while (cand) {
        int j = __ffsll((long long)cand) - 1;
        cand &= cand - 1;
        float4 cb = colBox[j];
        float y1 = fmaxf(rb.x, cb.x);
        float x1 = fmaxf(rb.y, cb.y);
        float y2 = fminf(rb.z, cb.z);
        float x2 = fminf(rb.w, cb.w);
        float inter = fmaxf(y2 - y1, 0.f) * fmaxf(x2 - x1, 0.f);
        float area2 = (cb.z - cb.x) * (cb.w - cb.y);
        float iou = inter / (area1 + area2 - inter + 1e-9f);
        if (iou > THR) m |= 1ull << j;
    }
    *maskOut = m;
    if (diagOut) *diagOut = m;
}

__global__ void iou_kernel() {
    int b = blockIdx.z;
    int C = blockIdx.x * 64;                 // column start
    int R = blockIdx.y * IOU_ROWS;           // row start
    if (R >= C + 64) return;                 // block fully below diagonal
    __shared__ float4 colBox[64];
    int tid = threadIdx.x;
    int ncols = min(64, TOPK - C);
    if (tid < ncols)
        colBox[tid] = reinterpret_cast<const float4*>(g_boxes)[b * TOPK + C + tid];
    __syncthreads();

    float4 rb[4];
    bool v[4];
    bool any = false;
    #pragma unroll
    for (int k = 0; k < 4; ++k) {
        int i = R + tid + (k << 8);
        v[k] = (i < TOPK) && (i < C + 64);
        any |= v[k];
        rb[k] = v[k] ? reinterpret_cast<const float4*>(g_boxes)[b * TOPK + i]
                     : make_float4(0.f, 0.f, 0.f, 0.f);
    }
    if (!any) return;

    unsigned lo[4] = {0, 0, 0, 0}, hi[4] = {0, 0, 0, 0};
    if (ncols == 64) {
        #pragma unroll
        for (int j = 0; j < 64; ++j) {
            float4 cb = colBox[j];
            #pragma unroll
            for (int k = 0; k < 4; ++k) {
                float ddy = fminf(rb[k].z, cb.z) - fmaxf(rb[k].x, cb.x);
                float ddx = fminf(rb[k].w, cb.w) - fmaxf(rb[k].y, cb.y);
                bool ov = (ddy > 0.f) && (ddx > 0.f);
                if (j < 32) lo[k] |= ov ? (1u << j) : 0u;
                else        hi[k] |= ov ? (1u << (j - 32)) : 0u;
            }
        }
    } else {
        for (int j = 0; j < ncols; ++j) {
            float4 cb = colBox[j];
            #pragma unroll
            for (int k = 0; k < 4; ++k) {
                float ddy = fminf(rb[k].z, cb.z) - fmaxf(rb[k].x, cb.x);
                float ddx = fminf(rb[k].w, cb.w) - fmaxf(rb[k].y, cb.y);
                bool ov = (ddy > 0.f) && (ddx > 0.f);
                if (j < 32) lo[k] |= ov ? (1u << j) : 0u;
                else        hi[k] |= ov ? (1u << (j - 32)) : 0u;
            }
        }
    }

    #pragma unroll
    for (int k = 0; k < 4; ++k) {
        if (!v[k]) continue;
        int i = R + tid + (k << 8);
        bool isDiag = ((i >> 6) == (C >> 6));
        unsigned long long* dout = isDiag ? &g_diag[b * TOPK + i] : nullptr;
        iou_row(colBox, rb[k],
                ((unsigned long long)hi[k] << 32) | lo[k],
                &g_mask[((size_t)(b * TOPK + i)) * COLB + blockIdx.x], dout);
    }
}

// -------- 6. sweep: smem chain (thread 0) + block-parallel batched row ORs -----
__global__ void __launch_bounds__(SWEEP_THREADS)
sweep_kernel(float* __restrict__ out) {
    extern __shared__ unsigned long long dsm[];
    unsigned long long* diag_sh = dsm;                 // TOPK u64 (48 KB)
    unsigned long long* rem_sh  = dsm + TOPK;          // COLB u64
    int* kept_sh = reinterpret_cast<int*>(rem_sh + COLB);  // NOUT ints
    int* ctrl    = kept_sh + NOUT;                     // [0]=m for this word

    int b = blockIdx.x;
    int tid = threadIdx.x;
    int warp = tid >> 5;
    int lane = tid & 31;
    constexpr int NWARP = SWEEP_THREADS / 32;

    for (int i = tid; i < TOPK; i += SWEEP_THREADS)
        diag_sh[i] = g_diag[b * TOPK + i];
    if (tid < COLB)
        rem_sh[tid] = (tid == COLB - 1) ? ~((1ull << TAIL_BITS) - 1ull) : 0ull;
    __syncthreads();

    int cnt = 0;
    for (int w = 0; w < COLB; ++w) {
        // Phase A (thread 0): resolve all kept bits of word w using smem only.
        if (tid == 0) {
            unsigned long long avail = ~rem_sh[w];
            int m = 0;
            while (avail && cnt + m < NOUT) {
                int bit = __ffsll((long long)avail) - 1;
                int i = (w << 6) + bit;
                kept_sh[cnt + m] = i;
                ++m;
                avail &= avail - 1;        // clear taken bit (zero-area safe)
                avail &= ~diag_sh[i];      // within-word forward suppression
            }
            ctrl[0] = m;
        }
        __syncthreads();
        int m = ctrl[0];
        // Phase B (whole block): OR the m kept rows into rem for words > w.
        for (int k = warp; k < m; k += NWARP) {
            const unsigned long long* row =
                &g_mask[((size_t)(b * TOPK + kept_sh[cnt + k])) * COLB];
            for (int ww = w + 1 + lane; ww < COLB; ww += 32)
                atomicOr(&rem_sh[ww], row[ww]);
        }
        cnt += m;
        if (cnt >= NOUT) break;           // uniform across block: safe
        __syncthreads();
    }
    __syncthreads();

    for (int k = tid; k < NOUT; k += SWEEP_THREADS) {
        float4 v = make_float4(0.f, 0.f, 0.f, 0.f);
        if (k < cnt)
            v = reinterpret_cast<const float4*>(g_boxes)[b * TOPK + kept_sh[k]];
        reinterpret_cast<float4*>(out)[b * NOUT + k] = v;
    }
}

// -------- launch --------------------------------------------------------------
extern "C" void kernel_launch(void* const* d_in, const int* in_sizes, int n_in,
                              void* d_out, int out_size) {
    const float* rpn_class = (const float*)d_in[0];
    const float* rpn_bbox  = (const float*)d_in[1];
    const float* anchors   = (const float*)d_in[2];
    float* out = (float*)d_out;

    void *histp, *cntp;
    cudaGetSymbolAddress(&histp, g_hist);
    cudaGetSymbolAddress(&cntp,  g_cnt);
    cudaMemsetAsync(histp, 0, sizeof(g_hist));
    cudaMemsetAsync(cntp,  0, sizeof(g_cnt));

    hist_kernel<<<TOTAL / 4 / 256, 256>>>((const float4*)rpn_class);
    thresh_kernel<<<BATCH, 256>>>();
    compact_kernel<<<TOTAL / 4 / 256, 256>>>((const float4*)rpn_class);

    constexpr int SORT_SMEM = (int)sizeof(typename BlockSortT::TempStorage);
    cudaFuncSetAttribute(sort_kernel,
                         cudaFuncAttributeMaxDynamicSharedMemorySize, SORT_SMEM);
    sort_kernel<<<BATCH, SORT_THREADS, SORT_SMEM>>>();

    boxes_kernel<<<(BATCH * TOPK + 255) / 256, 256>>>(rpn_bbox, anchors);

    dim3 gmask(COLB, (TOPK + IOU_ROWS - 1) / IOU_ROWS, BATCH);
    iou_kernel<<<gmask, 256>>>();

    cudaFuncSetAttribute(sweep_kernel,
                         cudaFuncAttributeMaxDynamicSharedMemorySize, SWEEP_SMEM);
    sweep_kernel<<<BATCH, SWEEP_THREADS, SWEEP_SMEM>>>(out);
}